// round 1
// baseline (speedup 1.0000x reference)
#include <cuda_runtime.h>
#include <math.h>

#define HIDDEN 1024
#define STATE  64
#define INTER  4096
#define BATCH  4
#define SEQ    2048
#define ROWS   (BATCH*SEQ)   // 8192

// ---------------- scratch (static device allocations; no cudaMalloc) ----------------
__device__ float g_hn1[ROWS*HIDDEN];    // rmsnorm1(x)
__device__ float g_h  [ROWS*HIDDEN];    // x + ssm_out   (residual for FFN)
__device__ float g_hn2[ROWS*HIDDEN];    // rmsnorm2(h)
__device__ float g_U  [ROWS*STATE];     // hn1 @ Bbar^T
__device__ float g_S  [ROWS*STATE];     // scan states
__device__ float g_act[ROWS*INTER];     // gate, then silu(gate)*up
__device__ float g_Bbar[STATE*HIDDEN];
__device__ float g_AbT [STATE*STATE];   // AbT[j*64+i] = A_bar[i][j]

// ---------------- prep: dt, mean(dt), Bbar, expm(A*mean_dt) ----------------
__global__ void prep_kernel(const float* __restrict__ A,
                            const float* __restrict__ B,
                            const float* __restrict__ log_dt)
{
    __shared__ float sm[12288];            // 48 KB exactly, reused across phases
    int tid = threadIdx.x;                 // 256 threads

    // phase 1: dt = exp(log_dt), mean(dt), Bbar = B * dt
    float* dts = sm;                       // [0,1024)
    float* red = sm + 1024;                // [1024,1280)
    float local = 0.f;
    for (int i = tid; i < HIDDEN; i += 256) {
        float d = expf(log_dt[i]);
        dts[i] = d;
        local += d;
    }
    red[tid] = local;
    __syncthreads();
    for (int s = 128; s > 0; s >>= 1) {
        if (tid < s) red[tid] += red[tid + s];
        __syncthreads();
    }
    float md = red[0] * (1.f / HIDDEN);    // mean(dt), kept in a register

    for (int e = tid; e < STATE*HIDDEN; e += 256)
        g_Bbar[e] = B[e] * dts[e & (HIDDEN - 1)];
    __syncthreads();                       // dts/red dead from here

    // phase 2: A_bar = expm(M), M = A*md.  ||M|| ~ 5e-3 -> 8-term Taylor is exact.
    float* Mm = sm;                        // [0,4096)
    float* T  = sm + 4096;                 // [4096,8192)
    float* R  = sm + 8192;                 // [8192,12288)
    for (int e = tid; e < 4096; e += 256) {
        float m = A[e] * md;
        Mm[e] = m; T[e] = m;
        int i = e >> 6, j = e & 63;
        R[e] = m + (i == j ? 1.f : 0.f);
    }
    __syncthreads();
    for (int k = 2; k <= 8; k++) {
        float inv = 1.f / (float)k;
        float val[16];
        #pragma unroll
        for (int c = 0; c < 16; c++) {
            int e = tid * 16 + c;
            int i = e >> 6, j = e & 63;
            float s2 = 0.f;
            for (int l = 0; l < 64; l++)
                s2 += T[i*64 + l] * Mm[l*64 + j];
            val[c] = s2 * inv;
        }
        __syncthreads();
        #pragma unroll
        for (int c = 0; c < 16; c++) {
            int e = tid * 16 + c;
            T[e] = val[c];
            R[e] += val[c];
        }
        __syncthreads();
    }
    for (int e = tid; e < 4096; e += 256) {
        int i = e >> 6, j = e & 63;
        g_AbT[j*64 + i] = R[i*64 + j];     // transposed for scan coalescing
    }
}

// ---------------- rmsnorm: one CTA per row, 256 threads x float4 ----------------
__global__ void rmsnorm_kernel(const float* __restrict__ x,
                               const float* __restrict__ w,
                               float* __restrict__ out)
{
    int row = blockIdx.x;
    const float4* xr = (const float4*)(x + (size_t)row * HIDDEN);
    float4 v = xr[threadIdx.x];
    float ss = v.x*v.x + v.y*v.y + v.z*v.z + v.w*v.w;
    #pragma unroll
    for (int o = 16; o > 0; o >>= 1) ss += __shfl_down_sync(0xffffffffu, ss, o);
    __shared__ float wr[8];
    __shared__ float sc;
    if ((threadIdx.x & 31) == 0) wr[threadIdx.x >> 5] = ss;
    __syncthreads();
    if (threadIdx.x == 0) {
        float t = 0.f;
        #pragma unroll
        for (int k = 0; k < 8; k++) t += wr[k];
        sc = rsqrtf(t * (1.f / HIDDEN) + 1e-6f);
    }
    __syncthreads();
    float s = sc;
    const float4* ww = (const float4*)w;
    float4 wv = ww[threadIdx.x];
    float4 o4 = make_float4(v.x*s*wv.x, v.y*s*wv.y, v.z*s*wv.z, v.w*s*wv.w);
    ((float4*)(out + (size_t)row * HIDDEN))[threadIdx.x] = o4;
}

// ---------------- sequential scan: 1 CTA per batch, state in smem ----------------
// new_state[i] = sum_j Abar[i][j]*state[j] + u[i];  256 thr = 64 i x 4 j-quarters
__global__ void scan_kernel()
{
    int b = blockIdx.x;
    const float* u  = g_U + (size_t)b * SEQ * STATE;
    float* sout     = g_S + (size_t)b * SEQ * STATE;

    __shared__ float st[64];
    __shared__ float part[4][64];
    __shared__ float ub[2][512];           // 8-step u prefetch ring

    int tid = threadIdx.x;
    int i = tid & 63, p = tid >> 6;

    float a[16];                           // this thread's slice of Abar
    #pragma unroll
    for (int jj = 0; jj < 16; jj++) a[jj] = g_AbT[(p*16 + jj)*64 + i];

    for (int e = tid; e < 512; e += 256) ub[0][e] = u[e];
    if (tid < 64) st[i] = 0.f;
    __syncthreads();

    for (int t = 0; t < SEQ; t++) {
        if ((t & 7) == 0) {
            int nb = (t >> 3) + 1;
            if (nb < SEQ/8) {
                int base = nb * 512;
                for (int e = tid; e < 512; e += 256) ub[nb & 1][e] = u[base + e];
            }
        }
        float acc = 0.f;
        #pragma unroll
        for (int jj = 0; jj < 16; jj++) acc += a[jj] * st[p*16 + jj];
        part[p][i] = acc;
        __syncthreads();
        if (tid < 64) {
            float v = part[0][i] + part[1][i] + part[2][i] + part[3][i]
                    + ub[(t >> 3) & 1][(t & 7)*64 + i];
            st[i] = v;
            sout[(size_t)t*STATE + i] = v;
        }
        __syncthreads();
    }
}

// ---------------- SGEMM: C[M,N] = A[M,K] @ B[N,K]^T, fused epilogues ----------------
// Tile 64x128x16, 256 threads, 8x4 micro-tile. A-reads warp-broadcast,
// B-reads contiguous float4 across lanes (conflict-free) -> FMA-issue bound.
#define BM 64
#define BN 128
#define BK 16
// modes: 0 plain; 1 out=res+acc+dvec[col]*extra; 2 out=silu(res)*acc; 3 out=res+acc
__global__ void __launch_bounds__(256) sgemm_kernel(
    const float* __restrict__ A, const float* __restrict__ Bm,
    int M, int N, int K, float* __restrict__ out, int mode,
    const float* __restrict__ res, const float* __restrict__ extra,
    const float* __restrict__ dvec)
{
    __shared__ float As[BK][BM];
    __shared__ float Bs[BK][BN];
    int tid = threadIdx.x;
    int m0 = blockIdx.y * BM, n0 = blockIdx.x * BN;

    int lr = tid >> 2;                     // 0..63
    int lk = (tid & 3) * 4;                // 0,4,8,12
    const float* Ap  = A  + (size_t)(m0 + lr) * K + lk;
    int bn1 = n0 + lr, bn2 = n0 + lr + 64;
    const float* Bp1 = Bm + (size_t)bn1 * K + lk;
    const float* Bp2 = Bm + (size_t)bn2 * K + lk;
    bool v1 = bn1 < N, v2 = bn2 < N;

    int wid = tid >> 5, lane = tid & 31;
    float acc[8][4];
    #pragma unroll
    for (int r = 0; r < 8; r++)
        #pragma unroll
        for (int c = 0; c < 4; c++) acc[r][c] = 0.f;

    const float4 z4 = make_float4(0.f, 0.f, 0.f, 0.f);
    for (int k0 = 0; k0 < K; k0 += BK) {
        float4 av = *(const float4*)(Ap + k0);
        float4 b1 = v1 ? *(const float4*)(Bp1 + k0) : z4;
        float4 b2 = v2 ? *(const float4*)(Bp2 + k0) : z4;
        As[lk+0][lr] = av.x; As[lk+1][lr] = av.y; As[lk+2][lr] = av.z; As[lk+3][lr] = av.w;
        Bs[lk+0][lr] = b1.x; Bs[lk+1][lr] = b1.y; Bs[lk+2][lr] = b1.z; Bs[lk+3][lr] = b1.w;
        Bs[lk+0][lr+64] = b2.x; Bs[lk+1][lr+64] = b2.y; Bs[lk+2][lr+64] = b2.z; Bs[lk+3][lr+64] = b2.w;
        __syncthreads();
        #pragma unroll
        for (int kk = 0; kk < BK; kk++) {
            float4 b  = *(const float4*)&Bs[kk][lane*4];
            float4 a0 = *(const float4*)&As[kk][wid*8];
            float4 a1 = *(const float4*)&As[kk][wid*8 + 4];
            float ar[8] = {a0.x,a0.y,a0.z,a0.w,a1.x,a1.y,a1.z,a1.w};
            float br[4] = {b.x,b.y,b.z,b.w};
            #pragma unroll
            for (int r = 0; r < 8; r++)
                #pragma unroll
                for (int c = 0; c < 4; c++)
                    acc[r][c] += ar[r] * br[c];
        }
        __syncthreads();
    }

    #pragma unroll
    for (int r = 0; r < 8; r++) {
        int row = m0 + wid*8 + r;
        #pragma unroll
        for (int c = 0; c < 4; c++) {
            int col = n0 + lane*4 + c;
            if (col < N) {
                size_t idx = (size_t)row * N + col;
                float v = acc[r][c];
                if (mode == 1)       v = res[idx] + v + dvec[col]*extra[idx];
                else if (mode == 2)  { float g = res[idx]; v = v * (g / (1.f + expf(-g))); }
                else if (mode == 3)  v = res[idx] + v;
                out[idx] = v;
            }
        }
    }
}

// ---------------- launch ----------------
extern "C" void kernel_launch(void* const* d_in, const int* in_sizes, int n_in,
                              void* d_out, int out_size)
{
    const float* x      = (const float*)d_in[0];
    const float* A      = (const float*)d_in[1];
    const float* B      = (const float*)d_in[2];
    const float* C      = (const float*)d_in[3];
    const float* D      = (const float*)d_in[4];
    const float* log_dt = (const float*)d_in[5];
    const float* w_gate = (const float*)d_in[6];
    const float* w_up   = (const float*)d_in[7];
    const float* w_down = (const float*)d_in[8];
    const float* ln1    = (const float*)d_in[9];
    const float* ln2    = (const float*)d_in[10];
    float* out = (float*)d_out;

    float *hn1, *h, *hn2, *U, *S, *act, *Bbar;
    cudaGetSymbolAddress((void**)&hn1,  g_hn1);
    cudaGetSymbolAddress((void**)&h,    g_h);
    cudaGetSymbolAddress((void**)&hn2,  g_hn2);
    cudaGetSymbolAddress((void**)&U,    g_U);
    cudaGetSymbolAddress((void**)&S,    g_S);
    cudaGetSymbolAddress((void**)&act,  g_act);
    cudaGetSymbolAddress((void**)&Bbar, g_Bbar);

    // 1. dt / Bbar / expm
    prep_kernel<<<1, 256>>>(A, B, log_dt);
    // 2. hn1 = rmsnorm(x, ln1)
    rmsnorm_kernel<<<ROWS, 256>>>(x, ln1, hn1);
    // 3. U = hn1 @ Bbar^T            (M=8192, N=64, K=1024)
    sgemm_kernel<<<dim3(1, ROWS/BM), 256>>>(hn1, Bbar, ROWS, STATE, HIDDEN,
                                            U, 0, nullptr, nullptr, nullptr);
    // 4. sequential scan -> S
    scan_kernel<<<BATCH, 256>>>();
    // 5. h = x + S @ C^T + D*hn1     (M=8192, N=1024, K=64)
    sgemm_kernel<<<dim3(HIDDEN/BN, ROWS/BM), 256>>>(S, C, ROWS, HIDDEN, STATE,
                                                    h, 1, x, hn1, D);
    // 6. hn2 = rmsnorm(h, ln2)
    rmsnorm_kernel<<<ROWS, 256>>>(h, ln2, hn2);
    // 7. gate = hn2 @ w_gate^T       (M=8192, N=4096, K=1024)
    sgemm_kernel<<<dim3(INTER/BN, ROWS/BM), 256>>>(hn2, w_gate, ROWS, INTER, HIDDEN,
                                                   act, 0, nullptr, nullptr, nullptr);
    // 8. act = silu(gate) * (hn2 @ w_up^T)
    sgemm_kernel<<<dim3(INTER/BN, ROWS/BM), 256>>>(hn2, w_up, ROWS, INTER, HIDDEN,
                                                   act, 2, act, nullptr, nullptr);
    // 9. out = h + act @ w_down^T    (M=8192, N=1024, K=4096)
    sgemm_kernel<<<dim3(HIDDEN/BN, ROWS/BM), 256>>>(act, w_down, ROWS, HIDDEN, INTER,
                                                    out, 3, h, nullptr, nullptr);
}

// round 2
// speedup vs baseline: 3.7071x; 3.7071x over previous
#include <cuda_runtime.h>
#include <math.h>
#include <stdint.h>

#define HIDDEN 1024
#define STATE  64
#define INTER  4096
#define BATCH  4
#define SEQ    2048
#define ROWS   (BATCH*SEQ)   // 8192
#define NCHUNK 32
#define CLEN   64            // NCHUNK*CLEN == SEQ

// ---------------- scratch (static device allocations; no cudaMalloc) ----------------
__device__ float g_hn1[ROWS*HIDDEN];
__device__ float g_h  [ROWS*HIDDEN];
__device__ float g_hn2[ROWS*HIDDEN];
__device__ float g_U  [ROWS*STATE];
__device__ float g_S  [ROWS*STATE];
__device__ float g_act[ROWS*INTER];
__device__ float g_Bbar[STATE*HIDDEN];
__device__ float g_AbT [STATE*STATE];     // AbT[j*64+i] = A_bar[i][j]
__device__ float g_A64T[STATE*STATE];     // A_bar^64, same transposed layout
__device__ float g_tail [BATCH*NCHUNK*STATE];
__device__ float g_carry[BATCH*NCHUNK*STATE];
__device__ float g_wg[INTER*HIDDEN];      // tf32-rounded weights
__device__ float g_wu[INTER*HIDDEN];
__device__ float g_wd[HIDDEN*INTER];

__device__ __forceinline__ float to_tf32(float x) {
    uint32_t u;
    asm("cvt.rna.tf32.f32 %0, %1;" : "=r"(u) : "f"(x));
    return __uint_as_float(u);
}

// ---------------- prep: dt, mean(dt), Bbar, expm(A*mean_dt) ----------------
__global__ void prep_kernel(const float* __restrict__ A,
                            const float* __restrict__ B,
                            const float* __restrict__ log_dt)
{
    __shared__ float sm[12288];
    int tid = threadIdx.x;                 // 256 threads

    float* dts = sm;
    float* red = sm + 1024;
    float local = 0.f;
    for (int i = tid; i < HIDDEN; i += 256) {
        float d = expf(log_dt[i]);
        dts[i] = d;
        local += d;
    }
    red[tid] = local;
    __syncthreads();
    for (int s = 128; s > 0; s >>= 1) {
        if (tid < s) red[tid] += red[tid + s];
        __syncthreads();
    }
    float md = red[0] * (1.f / HIDDEN);

    for (int e = tid; e < STATE*HIDDEN; e += 256)
        g_Bbar[e] = B[e] * dts[e & (HIDDEN - 1)];
    __syncthreads();

    // A_bar = expm(A*md), 8-term Taylor (||A*md|| ~ 3e-3 -> exact in fp32)
    float* Mm = sm;
    float* T  = sm + 4096;
    float* R  = sm + 8192;
    for (int e = tid; e < 4096; e += 256) {
        float m = A[e] * md;
        Mm[e] = m; T[e] = m;
        int i = e >> 6, j = e & 63;
        R[e] = m + (i == j ? 1.f : 0.f);
    }
    __syncthreads();
    for (int k = 2; k <= 8; k++) {
        float inv = 1.f / (float)k;
        float val[16];
        #pragma unroll
        for (int c = 0; c < 16; c++) {
            int e = tid * 16 + c;
            int i = e >> 6, j = e & 63;
            float s2 = 0.f;
            for (int l = 0; l < 64; l++)
                s2 += T[i*64 + l] * Mm[l*64 + j];
            val[c] = s2 * inv;
        }
        __syncthreads();
        #pragma unroll
        for (int c = 0; c < 16; c++) {
            int e = tid * 16 + c;
            T[e] = val[c];
            R[e] += val[c];
        }
        __syncthreads();
    }
    for (int e = tid; e < 4096; e += 256) {
        int i = e >> 6, j = e & 63;
        g_AbT[j*64 + i] = R[i*64 + j];
    }
}

// ---------------- A64 = A_bar^64 via 6 squarings (1 CTA) ----------------
__global__ void a64_kernel()
{
    __shared__ float P[4096], Q[4096];
    int tid = threadIdx.x;  // 256
    for (int e = tid; e < 4096; e += 256) {
        int i = e >> 6, j = e & 63;
        P[e] = g_AbT[j*64 + i];            // P[i][j] = A_bar[i][j]
    }
    __syncthreads();
    for (int s = 0; s < 6; s++) {
        float val[16];
        #pragma unroll
        for (int c = 0; c < 16; c++) {
            int e = tid*16 + c;
            int i = e >> 6, j = e & 63;
            float acc = 0.f;
            for (int l = 0; l < 64; l++)
                acc += P[i*64 + l] * P[l*64 + j];
            val[c] = acc;
        }
        __syncthreads();
        #pragma unroll
        for (int c = 0; c < 16; c++) Q[tid*16 + c] = val[c];
        __syncthreads();
        for (int e = tid; e < 4096; e += 256) P[e] = Q[e];
        __syncthreads();
    }
    for (int e = tid; e < 4096; e += 256) {
        int i = e >> 6, j = e & 63;
        g_A64T[j*64 + i] = P[i*64 + j];
    }
}

// ---------------- rmsnorm (optionally rounds output to tf32) ----------------
__global__ void rmsnorm_kernel(const float* __restrict__ x,
                               const float* __restrict__ w,
                               float* __restrict__ out, int round_tf32)
{
    int row = blockIdx.x;
    const float4* xr = (const float4*)(x + (size_t)row * HIDDEN);
    float4 v = xr[threadIdx.x];
    float ss = v.x*v.x + v.y*v.y + v.z*v.z + v.w*v.w;
    #pragma unroll
    for (int o = 16; o > 0; o >>= 1) ss += __shfl_down_sync(0xffffffffu, ss, o);
    __shared__ float wr[8];
    __shared__ float sc;
    if ((threadIdx.x & 31) == 0) wr[threadIdx.x >> 5] = ss;
    __syncthreads();
    if (threadIdx.x == 0) {
        float t = 0.f;
        #pragma unroll
        for (int k = 0; k < 8; k++) t += wr[k];
        sc = rsqrtf(t * (1.f / HIDDEN) + 1e-6f);
    }
    __syncthreads();
    float s = sc;
    const float4* ww = (const float4*)w;
    float4 wv = ww[threadIdx.x];
    float4 o4 = make_float4(v.x*s*wv.x, v.y*s*wv.y, v.z*s*wv.z, v.w*s*wv.w);
    if (round_tf32) {
        o4.x = to_tf32(o4.x); o4.y = to_tf32(o4.y);
        o4.z = to_tf32(o4.z); o4.w = to_tf32(o4.w);
    }
    ((float4*)(out + (size_t)row * HIDDEN))[threadIdx.x] = o4;
}

// ---------------- weight rounding to tf32 ----------------
__global__ void round_kernel(const float* __restrict__ in, float* __restrict__ out, int n)
{
    int i = blockIdx.x * 256 + threadIdx.x;
    int stride = gridDim.x * 256;
    for (; i < n; i += stride) out[i] = to_tf32(in[i]);
}

// ---------------- chunked scan ----------------
__global__ void local_scan_kernel()
{
    int c = blockIdx.x, b = blockIdx.y;
    const float* u = g_U + (size_t)(b*SEQ + c*CLEN) * STATE;
    float* sout    = g_S + (size_t)(b*SEQ + c*CLEN) * STATE;

    __shared__ float st[64];
    __shared__ float part[4][64];
    __shared__ float ub[CLEN*64];

    int tid = threadIdx.x;
    int i = tid & 63, p = tid >> 6;

    float a[16];
    #pragma unroll
    for (int jj = 0; jj < 16; jj++) a[jj] = g_AbT[(p*16 + jj)*64 + i];

    for (int e = tid; e < CLEN*64; e += 256) ub[e] = u[e];
    if (tid < 64) st[i] = 0.f;
    __syncthreads();

    for (int t = 0; t < CLEN; t++) {
        float acc = 0.f;
        #pragma unroll
        for (int jj = 0; jj < 16; jj++) acc += a[jj] * st[p*16 + jj];
        part[p][i] = acc;
        __syncthreads();
        if (tid < 64) {
            float v = part[0][i] + part[1][i] + part[2][i] + part[3][i] + ub[t*64 + i];
            st[i] = v;
            sout[(size_t)t*STATE + i] = v;
        }
        __syncthreads();
    }
    if (tid < 64) g_tail[(size_t)(b*NCHUNK + c)*STATE + i] = st[i];
}

__global__ void carry_kernel()
{
    int b = blockIdx.x;
    __shared__ float st[64];
    __shared__ float part[4][64];
    __shared__ float tails[NCHUNK*64];

    int tid = threadIdx.x;
    int i = tid & 63, p = tid >> 6;

    float a[16];
    #pragma unroll
    for (int jj = 0; jj < 16; jj++) a[jj] = g_A64T[(p*16 + jj)*64 + i];

    for (int e = tid; e < NCHUNK*64; e += 256)
        tails[e] = g_tail[(size_t)b*NCHUNK*STATE + e];
    if (tid < 64) {
        st[i] = 0.f;
        g_carry[(size_t)b*NCHUNK*STATE + i] = 0.f;   // carry[0] = 0
    }
    __syncthreads();

    for (int c = 1; c < NCHUNK; c++) {
        float acc = 0.f;
        #pragma unroll
        for (int jj = 0; jj < 16; jj++) acc += a[jj] * st[p*16 + jj];
        part[p][i] = acc;
        __syncthreads();
        if (tid < 64) {
            float v = part[0][i] + part[1][i] + part[2][i] + part[3][i]
                    + tails[(c-1)*64 + i];
            st[i] = v;
            g_carry[(size_t)(b*NCHUNK + c)*STATE + i] = v;
        }
        __syncthreads();
    }
}

__global__ void fixup_kernel()
{
    int c = blockIdx.x, b = blockIdx.y;
    float* sout = g_S + (size_t)(b*SEQ + c*CLEN) * STATE;

    __shared__ float st[64];
    __shared__ float part[4][64];

    int tid = threadIdx.x;
    int i = tid & 63, p = tid >> 6;

    float a[16];
    #pragma unroll
    for (int jj = 0; jj < 16; jj++) a[jj] = g_AbT[(p*16 + jj)*64 + i];

    if (tid < 64) st[i] = g_carry[(size_t)(b*NCHUNK + c)*STATE + i];
    __syncthreads();

    for (int t = 0; t < CLEN; t++) {
        float acc = 0.f;
        #pragma unroll
        for (int jj = 0; jj < 16; jj++) acc += a[jj] * st[p*16 + jj];
        part[p][i] = acc;
        __syncthreads();
        if (tid < 64) {
            float v = part[0][i] + part[1][i] + part[2][i] + part[3][i];
            st[i] = v;
            sout[(size_t)t*STATE + i] += v;
        }
        __syncthreads();
    }
}

// ---------------- SIMT SGEMM (small GEMMs + mode-1 epilogue) ----------------
#define BM 64
#define BN 128
#define BK 16
__global__ void __launch_bounds__(256) sgemm_kernel(
    const float* __restrict__ A, const float* __restrict__ Bm,
    int M, int N, int K, float* __restrict__ out, int mode,
    const float* __restrict__ res, const float* __restrict__ extra,
    const float* __restrict__ dvec)
{
    __shared__ float As[BK][BM];
    __shared__ float Bs[BK][BN];
    int tid = threadIdx.x;
    int m0 = blockIdx.y * BM, n0 = blockIdx.x * BN;

    int lr = tid >> 2;
    int lk = (tid & 3) * 4;
    const float* Ap  = A  + (size_t)(m0 + lr) * K + lk;
    int bn1 = n0 + lr, bn2 = n0 + lr + 64;
    const float* Bp1 = Bm + (size_t)bn1 * K + lk;
    const float* Bp2 = Bm + (size_t)bn2 * K + lk;
    bool v1 = bn1 < N, v2 = bn2 < N;

    int wid = tid >> 5, lane = tid & 31;
    float acc[8][4];
    #pragma unroll
    for (int r = 0; r < 8; r++)
        #pragma unroll
        for (int c = 0; c < 4; c++) acc[r][c] = 0.f;

    const float4 z4 = make_float4(0.f, 0.f, 0.f, 0.f);
    for (int k0 = 0; k0 < K; k0 += BK) {
        float4 av = *(const float4*)(Ap + k0);
        float4 b1 = v1 ? *(const float4*)(Bp1 + k0) : z4;
        float4 b2 = v2 ? *(const float4*)(Bp2 + k0) : z4;
        As[lk+0][lr] = av.x; As[lk+1][lr] = av.y; As[lk+2][lr] = av.z; As[lk+3][lr] = av.w;
        Bs[lk+0][lr] = b1.x; Bs[lk+1][lr] = b1.y; Bs[lk+2][lr] = b1.z; Bs[lk+3][lr] = b1.w;
        Bs[lk+0][lr+64] = b2.x; Bs[lk+1][lr+64] = b2.y; Bs[lk+2][lr+64] = b2.z; Bs[lk+3][lr+64] = b2.w;
        __syncthreads();
        #pragma unroll
        for (int kk = 0; kk < BK; kk++) {
            float4 b  = *(const float4*)&Bs[kk][lane*4];
            float4 a0 = *(const float4*)&As[kk][wid*8];
            float4 a1 = *(const float4*)&As[kk][wid*8 + 4];
            float ar[8] = {a0.x,a0.y,a0.z,a0.w,a1.x,a1.y,a1.z,a1.w};
            float br[4] = {b.x,b.y,b.z,b.w};
            #pragma unroll
            for (int r = 0; r < 8; r++)
                #pragma unroll
                for (int c = 0; c < 4; c++)
                    acc[r][c] += ar[r] * br[c];
        }
        __syncthreads();
    }

    #pragma unroll
    for (int r = 0; r < 8; r++) {
        int row = m0 + wid*8 + r;
        #pragma unroll
        for (int c = 0; c < 4; c++) {
            int col = n0 + lane*4 + c;
            if (col < N) {
                size_t idx = (size_t)row * N + col;
                float v = acc[r][c];
                if (mode == 1) v = res[idx] + v + dvec[col]*extra[idx];
                out[idx] = v;
            }
        }
    }
}

// ---------------- tf32 tensor-core GEMM: C = A[M,K] @ B[N,K]^T ----------------
__device__ __forceinline__ void cp16(float* s, const float* g) {
    uint32_t sa = (uint32_t)__cvta_generic_to_shared(s);
    asm volatile("cp.async.cg.shared.global [%0], [%1], 16;\n" :: "r"(sa), "l"(g));
}
__device__ __forceinline__ void mma_tf32(float* d,
    uint32_t a0, uint32_t a1, uint32_t a2, uint32_t a3, uint32_t b0, uint32_t b1)
{
    asm volatile(
        "mma.sync.aligned.m16n8k8.row.col.f32.tf32.tf32.f32 "
        "{%0,%1,%2,%3}, {%4,%5,%6,%7}, {%8,%9}, {%0,%1,%2,%3};\n"
        : "+f"(d[0]), "+f"(d[1]), "+f"(d[2]), "+f"(d[3])
        : "r"(a0), "r"(a1), "r"(a2), "r"(a3), "r"(b0), "r"(b1));
}

// modes: 0 plain; 2 out = tf32(silu(res)*acc); 3 out = res + acc
__global__ void __launch_bounds__(256) gemm_tf32(
    const float* __restrict__ A, const float* __restrict__ Bm,
    int M, int N, int K, float* __restrict__ out, int mode,
    const float* __restrict__ res)
{
    extern __shared__ float sm[];          // 2 stages x (A 4096 + B 4096) floats = 64KB
    int tid = threadIdx.x;
    int m0 = blockIdx.y * 128, n0 = blockIdx.x * 128;

    int lrow = tid >> 3, k4 = tid & 7;
    const float* Ag = A  + (size_t)(m0 + lrow) * K + k4*4;
    const float* Bg = Bm + (size_t)(n0 + lrow) * K + k4*4;

    int lane = tid & 31, warp = tid >> 5;
    int wm = warp & 1, wn = warp >> 1;     // 2 x 4 warp grid, warp tile 64x32
    int gid = lane >> 2, tig = lane & 3;

    float acc[4][4][4];
    #pragma unroll
    for (int mt = 0; mt < 4; mt++)
        #pragma unroll
        for (int nt = 0; nt < 4; nt++)
            #pragma unroll
            for (int r = 0; r < 4; r++) acc[mt][nt][r] = 0.f;

    int NT = K >> 5;

    #define LOAD_STAGE(kt, s) do {                                            \
        float* As_ = sm + (s)*8192;                                           \
        float* Bs_ = As_ + 4096;                                              \
        int k0_ = (kt) << 5;                                                  \
        _Pragma("unroll")                                                     \
        for (int p_ = 0; p_ < 4; p_++) {                                      \
            int r_ = lrow + p_*32;                                            \
            int slot_ = r_*8 + (k4 ^ (r_ & 7));                               \
            cp16(As_ + slot_*4, Ag + (size_t)p_*32*K + k0_);                  \
            cp16(Bs_ + slot_*4, Bg + (size_t)p_*32*K + k0_);                  \
        }                                                                     \
        asm volatile("cp.async.commit_group;\n");                             \
    } while (0)

    LOAD_STAGE(0, 0);

    for (int kt = 0; kt < NT; kt++) {
        if (kt + 1 < NT) {
            LOAD_STAGE(kt + 1, (kt + 1) & 1);
            asm volatile("cp.async.wait_group 1;\n");
        } else {
            asm volatile("cp.async.wait_group 0;\n");
        }
        __syncthreads();

        const float* As = sm + (kt & 1)*8192;
        const float* Bs = As + 4096;

        #pragma unroll
        for (int ks = 0; ks < 4; ks++) {
            uint32_t bf[4][2];
            #pragma unroll
            for (int nt = 0; nt < 4; nt++) {
                int c = wn*32 + nt*8 + gid;
                bf[nt][0] = __float_as_uint(Bs[c*32 + (((2*ks)   ^ (c & 7)) << 2) + tig]);
                bf[nt][1] = __float_as_uint(Bs[c*32 + (((2*ks+1) ^ (c & 7)) << 2) + tig]);
            }
            #pragma unroll
            for (int mt = 0; mt < 4; mt++) {
                int r = wm*64 + mt*16 + gid;
                int r8 = r + 8;
                uint32_t a0 = __float_as_uint(As[r *32 + (((2*ks)   ^ (r  & 7)) << 2) + tig]);
                uint32_t a1 = __float_as_uint(As[r8*32 + (((2*ks)   ^ (r8 & 7)) << 2) + tig]);
                uint32_t a2 = __float_as_uint(As[r *32 + (((2*ks+1) ^ (r  & 7)) << 2) + tig]);
                uint32_t a3 = __float_as_uint(As[r8*32 + (((2*ks+1) ^ (r8 & 7)) << 2) + tig]);
                #pragma unroll
                for (int nt = 0; nt < 4; nt++)
                    mma_tf32(acc[mt][nt], a0, a1, a2, a3, bf[nt][0], bf[nt][1]);
            }
        }
        __syncthreads();
    }
    #undef LOAD_STAGE

    #pragma unroll
    for (int mt = 0; mt < 4; mt++) {
        #pragma unroll
        for (int nt = 0; nt < 4; nt++) {
            int row0 = m0 + wm*64 + mt*16 + gid;
            int col0 = n0 + wn*32 + nt*8 + tig*2;
            #pragma unroll
            for (int half = 0; half < 2; half++) {
                int row = row0 + half*8;
                size_t idx = (size_t)row * N + col0;
                float v0 = acc[mt][nt][half*2 + 0];
                float v1 = acc[mt][nt][half*2 + 1];
                if (mode == 2) {
                    float gg0 = res[idx], gg1 = res[idx + 1];
                    v0 = to_tf32(v0 * (gg0 / (1.f + expf(-gg0))));
                    v1 = to_tf32(v1 * (gg1 / (1.f + expf(-gg1))));
                } else if (mode == 3) {
                    v0 += res[idx];
                    v1 += res[idx + 1];
                }
                *(float2*)(out + idx) = make_float2(v0, v1);
            }
        }
    }
}

// ---------------- launch ----------------
extern "C" void kernel_launch(void* const* d_in, const int* in_sizes, int n_in,
                              void* d_out, int out_size)
{
    const float* x      = (const float*)d_in[0];
    const float* A      = (const float*)d_in[1];
    const float* B      = (const float*)d_in[2];
    const float* C      = (const float*)d_in[3];
    const float* D      = (const float*)d_in[4];
    const float* log_dt = (const float*)d_in[5];
    const float* w_gate = (const float*)d_in[6];
    const float* w_up   = (const float*)d_in[7];
    const float* w_down = (const float*)d_in[8];
    const float* ln1    = (const float*)d_in[9];
    const float* ln2    = (const float*)d_in[10];
    float* out = (float*)d_out;

    float *hn1, *h, *hn2, *U, *S, *act, *Bbar, *wg, *wu, *wd;
    cudaGetSymbolAddress((void**)&hn1,  g_hn1);
    cudaGetSymbolAddress((void**)&h,    g_h);
    cudaGetSymbolAddress((void**)&hn2,  g_hn2);
    cudaGetSymbolAddress((void**)&U,    g_U);
    cudaGetSymbolAddress((void**)&S,    g_S);
    cudaGetSymbolAddress((void**)&act,  g_act);
    cudaGetSymbolAddress((void**)&Bbar, g_Bbar);
    cudaGetSymbolAddress((void**)&wg,   g_wg);
    cudaGetSymbolAddress((void**)&wu,   g_wu);
    cudaGetSymbolAddress((void**)&wd,   g_wd);

    cudaFuncSetAttribute(gemm_tf32, cudaFuncAttributeMaxDynamicSharedMemorySize, 65536);
    const int DSMEM = 65536;

    // weight rounding (independent of SSM path)
    round_kernel<<<512, 256>>>(w_gate, wg, INTER*HIDDEN);
    round_kernel<<<512, 256>>>(w_up,   wu, INTER*HIDDEN);
    round_kernel<<<512, 256>>>(w_down, wd, HIDDEN*INTER);

    // SSM path
    prep_kernel<<<1, 256>>>(A, B, log_dt);
    rmsnorm_kernel<<<ROWS, 256>>>(x, ln1, hn1, 0);
    sgemm_kernel<<<dim3(1, ROWS/BM), 256>>>(hn1, Bbar, ROWS, STATE, HIDDEN,
                                            U, 0, nullptr, nullptr, nullptr);
    local_scan_kernel<<<dim3(NCHUNK, BATCH), 256>>>();
    a64_kernel<<<1, 256>>>();
    carry_kernel<<<BATCH, 256>>>();
    fixup_kernel<<<dim3(NCHUNK, BATCH), 256>>>();
    // h = x + S @ C^T + D*hn1
    sgemm_kernel<<<dim3(HIDDEN/BN, ROWS/BM), 256>>>(S, C, ROWS, HIDDEN, STATE,
                                                    h, 1, x, hn1, D);
    // FFN (tf32 tensor cores)
    rmsnorm_kernel<<<ROWS, 256>>>(h, ln2, hn2, 1);
    gemm_tf32<<<dim3(INTER/128, ROWS/128), 256, DSMEM>>>(hn2, wg, ROWS, INTER, HIDDEN,
                                                         act, 0, nullptr);
    gemm_tf32<<<dim3(INTER/128, ROWS/128), 256, DSMEM>>>(hn2, wu, ROWS, INTER, HIDDEN,
                                                         act, 2, act);
    gemm_tf32<<<dim3(HIDDEN/128, ROWS/128), 256, DSMEM>>>(act, wd, ROWS, HIDDEN, INTER,
                                                          out, 3, h);
}